// round 9
// baseline (speedup 1.0000x reference)
#include <cuda_runtime.h>
#include <cstdint>

#define BB 128
#define SS 4096
#define TT 64

// Scratch (no cudaMalloc allowed)
__device__ float g_num[BB];
__device__ float g_den[BB];
__device__ int   g_len[BB];

typedef unsigned long long u64;

// ---------------- packed f32x2 helpers ----------------
__device__ __forceinline__ u64 pack2(float lo, float hi) {
    u64 r;
    asm("mov.b64 %0, {%1, %2};" : "=l"(r) : "f"(lo), "f"(hi));
    return r;
}
__device__ __forceinline__ void unpack2(u64 p, float& lo, float& hi) {
    asm("mov.b64 {%0, %1}, %2;" : "=f"(lo), "=f"(hi) : "l"(p));
}
__device__ __forceinline__ void fma2(u64& d, u64 a, u64 b) {
    asm("fma.rn.f32x2 %0, %1, %2, %0;" : "+l"(d) : "l"(a), "l"(b));
}
__device__ __forceinline__ u64 mul2(u64 a, u64 b) {
    u64 d;
    asm("mul.rn.f32x2 %0, %1, %2;" : "=l"(d) : "l"(a), "l"(b));
    return d;
}
__device__ __forceinline__ u64 add2(u64 a, u64 b) {
    u64 d;
    asm("add.rn.f32x2 %0, %1, %2;" : "=l"(d) : "l"(a), "l"(b));
    return d;
}

// ---------------- kernel 1: numerator + lengths (1024 threads for MLP) ----------------
__global__ void __launch_bounds__(1024)
crf_numer_kernel(const float* __restrict__ logits,
                 const int* __restrict__ tags,
                 const void* __restrict__ mask,
                 const float* __restrict__ trans,
                 const float* __restrict__ start_t,
                 const float* __restrict__ end_t) {
    const int b = blockIdx.x;
    const int tid = threadIdx.x;
    const int NT = 1024;

    const bool m32 = (((const int*)mask)[0] == 1);  // int32 vs uint8 layout
    const float* lg = logits + (size_t)b * SS * TT;
    const int* tg = tags + b * SS;
    const unsigned char* mk8 = ((const unsigned char*)mask) + (size_t)b * SS;
    const int* mk32 = ((const int*)mask) + (size_t)b * SS;

    float sum = 0.f;
    int cnt = 0;
#pragma unroll
    for (int k = 0; k < SS / NT; k++) {
        int t = tid + k * NT;
        int m = m32 ? (mk32[t] != 0) : (mk8[t] != 0);
        cnt += m;
        if (m) {
            int tagt = tg[t];
            sum += lg[(size_t)t * TT + tagt];
            if (t > 0) sum += trans[tg[t - 1] * TT + tagt];
        }
    }
#pragma unroll
    for (int o = 16; o > 0; o >>= 1) {
        sum += __shfl_down_sync(0xffffffffu, sum, o);
        cnt += __shfl_down_sync(0xffffffffu, cnt, o);
    }
    __shared__ float ssum[32];
    __shared__ int scnt[32];
    if ((tid & 31) == 0) { ssum[tid >> 5] = sum; scnt[tid >> 5] = cnt; }
    __syncthreads();
    if (tid < 32) {
        float s2 = ssum[tid];
        int c2 = scnt[tid];
#pragma unroll
        for (int o = 16; o > 0; o >>= 1) {
            s2 += __shfl_down_sync(0xffffffffu, s2, o);
            c2 += __shfl_down_sync(0xffffffffu, c2, o);
        }
        if (tid == 0) {
            int L = c2;
            s2 += start_t[tg[0]] + end_t[tg[L - 1]];
            g_num[b] = s2;
            g_len[b] = L;
        }
    }
}

// ---------------- one forward-scan step (single warp, 2 cols/thread) ----------------
// Thread L computes columns j0=2L, j1=2L+1 over all 64 i-terms (32 f32x2 pairs).
// Exchange is intra-warp: __syncwarp + LDS.128 broadcast (u arrives as i-pairs).
__device__ __forceinline__ void crf_step1w(const u64 (&ea)[32], const u64 (&eb)[32],
                                           const float* __restrict__ ur,
                                           float* __restrict__ uw,
                                           int j0, u64 g2, int& eacc) {
    __syncwarp();
    u64 Aa[4], Ab[4];
    int E;
    float r;
    {
        ulonglong2 pq = *reinterpret_cast<const ulonglong2*>(ur);
        Aa[0] = mul2(pq.x, ea[0]);  Ab[0] = mul2(pq.x, eb[0]);
        Aa[1] = mul2(pq.y, ea[1]);  Ab[1] = mul2(pq.y, eb[1]);
        // Exact power-of-2 rescale from exponent of u[0] (low word of first pair)
        unsigned ub = (unsigned)pq.x;
        E = (int)(ub >> 23);
        r = __uint_as_float((unsigned)(254 - E) << 23);
    }
    {
        ulonglong2 pq = *reinterpret_cast<const ulonglong2*>(ur + 4);
        Aa[2] = mul2(pq.x, ea[2]);  Ab[2] = mul2(pq.x, eb[2]);
        Aa[3] = mul2(pq.y, ea[3]);  Ab[3] = mul2(pq.y, eb[3]);
    }
#pragma unroll
    for (int q = 2; q < 16; q++) {
        ulonglong2 pq = *reinterpret_cast<const ulonglong2*>(ur + 4 * q);
        const int i2 = 2 * q;
        fma2(Aa[i2 & 3],       pq.x, ea[i2]);
        fma2(Ab[i2 & 3],       pq.x, eb[i2]);
        fma2(Aa[(i2 + 1) & 3], pq.y, ea[i2 + 1]);
        fma2(Ab[(i2 + 1) & 3], pq.y, eb[i2 + 1]);
    }
    eacc += E - 127;
    u64 ta = add2(add2(Aa[0], Aa[1]), add2(Aa[2], Aa[3]));
    u64 tb = add2(add2(Ab[0], Ab[1]), add2(Ab[2], Ab[3]));
    float alo, ahi, blo, bhi;
    unpack2(ta, alo, ahi);
    unpack2(tb, blo, bhi);
    u64 v2 = mul2(pack2(alo + ahi, blo + bhi), mul2(g2, pack2(r, r)));
    *reinterpret_cast<u64*>(uw + j0) = v2;   // STS.64, consecutive columns
}

// ---------------- kernel 2: forward scan (denominator), 32 threads ----------------
__global__ void __launch_bounds__(32, 1)
crf_scan_kernel(const float* __restrict__ logits,
                const float* __restrict__ trans,
                const float* __restrict__ start_t,
                const float* __restrict__ end_t) {
    const int b = blockIdx.x;
    const int lam = threadIdx.x;        // 0..31
    const int j0 = 2 * lam;
    const int j1 = j0 + 1;
    const float* lg = logits + (size_t)b * SS * TT;
    const int L = g_len[b];

    // E columns j0, j1: 32 i-pairs each, packed f32x2
    u64 ea[32], eb[32];
#pragma unroll
    for (int i2 = 0; i2 < 32; i2++) {
        const float* tr = trans + (2 * i2) * TT;
        ea[i2] = pack2(__expf(tr[j0]), __expf(tr[TT + j0]));
        eb[i2] = pack2(__expf(tr[j1]), __expf(tr[TT + j1]));
    }

    __shared__ __align__(16) float ubuf[2][TT];

    // alpha0 = start + logits[:,0] (linear domain)
    {
        float2 l0 = *reinterpret_cast<const float2*>(lg + j0);
        float v0 = __expf(start_t[j0] + l0.x);
        float v1 = __expf(start_t[j1] + l0.y);
        *reinterpret_cast<u64*>(&ubuf[1][j0]) = pack2(v0, v1);
    }
    int eacc = 0;

    // Two-stage pipeline: raw logits loaded 16 steps ahead, exp'd 8 steps ahead.
    float2 raw[8];
    u64 gq[8];
#pragma unroll
    for (int k = 0; k < 8; k++) {
        float2 r0 = *reinterpret_cast<const float2*>(lg + (size_t)(1 + k) * TT + j0);
        gq[k] = pack2(__expf(r0.x), __expf(r0.y));
    }
#pragma unroll
    for (int k = 0; k < 8; k++)
        raw[k] = *reinterpret_cast<const float2*>(lg + (size_t)(9 + k) * TT + j0);

    int t = 1;
    for (; t + 8 <= L; t += 8) {
#pragma unroll
        for (int k = 0; k < 8; k++) {
            const int rb = (1 + k) & 1;  // t stays odd: rb = (t+k)&1
            crf_step1w(ea, eb, ubuf[rb], ubuf[rb ^ 1], j0, gq[k], eacc);
            gq[k] = pack2(__expf(raw[k].x), __expf(raw[k].y));   // for step t+k+8
            int nt = t + k + 16;                                  // for step t+k+16
            nt = (nt < SS - 1) ? nt : (SS - 1);
            raw[k] = *reinterpret_cast<const float2*>(lg + (size_t)nt * TT + j0);
        }
    }
    {
        const int rem = L - t;
#pragma unroll
        for (int k = 0; k < 8; k++) {
            if (k < rem) {
                const int rb = (1 + k) & 1;
                crf_step1w(ea, eb, ubuf[rb], ubuf[rb ^ 1], j0, gq[k], eacc);
            }
        }
    }

    // den = eacc*ln2 + log( sum_j v_j * exp(end_j) ); final alpha in ubuf[L&1]
    __syncwarp();
    const float* uf = ubuf[L & 1];
    float z = uf[j0] * __expf(end_t[j0]) + uf[j1] * __expf(end_t[j1]);
#pragma unroll
    for (int o = 16; o > 0; o >>= 1)
        z += __shfl_down_sync(0xffffffffu, z, o);
    if (lam == 0)
        g_den[b] = (float)eacc * 0.6931471805599453f + __logf(z);
}

// ---------------- kernel 3: deterministic final reduction ----------------
__global__ void crf_finish_kernel(float* __restrict__ out) {
    const int i = threadIdx.x;  // 128 threads
    float d = g_num[i] - g_den[i];
#pragma unroll
    for (int o = 16; o > 0; o >>= 1)
        d += __shfl_down_sync(0xffffffffu, d, o);
    __shared__ float ws[4];
    if ((i & 31) == 0) ws[i >> 5] = d;
    __syncthreads();
    if (i == 0) out[0] = (ws[0] + ws[1]) + (ws[2] + ws[3]);
}

// ---------------- launch ----------------
extern "C" void kernel_launch(void* const* d_in, const int* in_sizes, int n_in,
                              void* d_out, int out_size) {
    const float* logits = (const float*)d_in[0];
    const int* tags     = (const int*)d_in[1];
    const void* mask    = d_in[2];
    const float* trans  = (const float*)d_in[3];
    const float* startt = (const float*)d_in[4];
    const float* endt   = (const float*)d_in[5];
    float* out = (float*)d_out;

    crf_numer_kernel<<<BB, 1024>>>(logits, tags, mask, trans, startt, endt);
    crf_scan_kernel<<<BB, 32>>>(logits, trans, startt, endt);
    crf_finish_kernel<<<1, 128>>>(out);
}

// round 10
// speedup vs baseline: 1.1680x; 1.1680x over previous
#include <cuda_runtime.h>
#include <cstdint>

#define BB 128
#define SS 4096
#define TT 64

// Scratch (no cudaMalloc allowed)
__device__ float g_num[BB];
__device__ float g_den[BB];
__device__ int   g_len[BB];

typedef unsigned long long u64;

// ---------------- packed f32x2 helpers ----------------
__device__ __forceinline__ u64 pack2(float lo, float hi) {
    u64 r;
    asm("mov.b64 %0, {%1, %2};" : "=l"(r) : "f"(lo), "f"(hi));
    return r;
}
__device__ __forceinline__ void unpack2(u64 p, float& lo, float& hi) {
    asm("mov.b64 {%0, %1}, %2;" : "=f"(lo), "=f"(hi) : "l"(p));
}
__device__ __forceinline__ void fma2(u64& d, u64 a, u64 b) {
    asm("fma.rn.f32x2 %0, %1, %2, %0;" : "+l"(d) : "l"(a), "l"(b));
}
__device__ __forceinline__ u64 mul2(u64 a, u64 b) {
    u64 d;
    asm("mul.rn.f32x2 %0, %1, %2;" : "=l"(d) : "l"(a), "l"(b));
    return d;
}
__device__ __forceinline__ u64 add2(u64 a, u64 b) {
    u64 d;
    asm("add.rn.f32x2 %0, %1, %2;" : "=l"(d) : "l"(a), "l"(b));
    return d;
}

// ---------------- kernel 1: numerator + lengths (1024 threads for MLP) ----------------
__global__ void __launch_bounds__(1024)
crf_numer_kernel(const float* __restrict__ logits,
                 const int* __restrict__ tags,
                 const void* __restrict__ mask,
                 const float* __restrict__ trans,
                 const float* __restrict__ start_t,
                 const float* __restrict__ end_t) {
    const int b = blockIdx.x;
    const int tid = threadIdx.x;
    const int NT = 1024;

    const bool m32 = (((const int*)mask)[0] == 1);  // int32 vs uint8 layout
    const float* lg = logits + (size_t)b * SS * TT;
    const int* tg = tags + b * SS;
    const unsigned char* mk8 = ((const unsigned char*)mask) + (size_t)b * SS;
    const int* mk32 = ((const int*)mask) + (size_t)b * SS;

    float sum = 0.f;
    int cnt = 0;
#pragma unroll
    for (int k = 0; k < SS / NT; k++) {
        int t = tid + k * NT;
        int m = m32 ? (mk32[t] != 0) : (mk8[t] != 0);
        cnt += m;
        if (m) {
            int tagt = tg[t];
            sum += lg[(size_t)t * TT + tagt];
            if (t > 0) sum += trans[tg[t - 1] * TT + tagt];
        }
    }
#pragma unroll
    for (int o = 16; o > 0; o >>= 1) {
        sum += __shfl_down_sync(0xffffffffu, sum, o);
        cnt += __shfl_down_sync(0xffffffffu, cnt, o);
    }
    __shared__ float ssum[32];
    __shared__ int scnt[32];
    if ((tid & 31) == 0) { ssum[tid >> 5] = sum; scnt[tid >> 5] = cnt; }
    __syncthreads();
    if (tid < 32) {
        float s2 = ssum[tid];
        int c2 = scnt[tid];
#pragma unroll
        for (int o = 16; o > 0; o >>= 1) {
            s2 += __shfl_down_sync(0xffffffffu, s2, o);
            c2 += __shfl_down_sync(0xffffffffu, c2, o);
        }
        if (tid == 0) {
            int L = c2;
            s2 += start_t[tg[0]] + end_t[tg[L - 1]];
            g_num[b] = s2;
            g_len[b] = L;
        }
    }
}

// ---------------- one forward-scan step (partial-pair state) ----------------
// Shared state: P[i] = float2 (P0_i, P1_i), u_i = P0_i + P1_i.
// Thread (j,p) computes partial_p[j] = sum_{i in [32p,32p+32)} u_i * E_ij,
// scales by g_t[j] * r (exact pow2 rescale keyed on P0[0]'s exponent),
// and stores it as component p of P'[j]. No cross-thread combine on the chain.
__device__ __forceinline__ void crf_stepP(const u64 (&e2)[32],
                                          const float* __restrict__ pr,  // read buf (float2[64])
                                          float* __restrict__ pw,        // write buf
                                          int p, int j, float gex, int& eacc) {
    __syncthreads();
    const float* base = pr + 64 * p;   // float2 i-range [32p, 32p+32)
    u64 A[8];
    int E;
    {
        ulonglong2 q0 = *reinterpret_cast<const ulonglong2*>(base);
        ulonglong2 q1 = *reinterpret_cast<const ulonglong2*>(base + 4);
        ulonglong2 q2 = *reinterpret_cast<const ulonglong2*>(base + 8);
        ulonglong2 q3 = *reinterpret_cast<const ulonglong2*>(base + 12);
        A[0] = mul2(q0.x, e2[0]);  A[1] = mul2(q0.y, e2[1]);
        A[2] = mul2(q1.x, e2[2]);  A[3] = mul2(q1.y, e2[3]);
        A[4] = mul2(q2.x, e2[4]);  A[5] = mul2(q2.y, e2[5]);
        A[6] = mul2(q3.x, e2[6]);  A[7] = mul2(q3.y, e2[7]);
    }
    // exponent of previous P0[0] (positive); all threads read it (broadcast LDS.32)
    E = ((int)__float_as_uint(pr[0])) >> 23;
#pragma unroll
    for (int q = 4; q < 16; q += 4) {
        ulonglong2 q0 = *reinterpret_cast<const ulonglong2*>(base + 4 * q);
        ulonglong2 q1 = *reinterpret_cast<const ulonglong2*>(base + 4 * q + 4);
        ulonglong2 q2 = *reinterpret_cast<const ulonglong2*>(base + 4 * q + 8);
        ulonglong2 q3 = *reinterpret_cast<const ulonglong2*>(base + 4 * q + 12);
        fma2(A[0], q0.x, e2[2 * q]);      fma2(A[1], q0.y, e2[2 * q + 1]);
        fma2(A[2], q1.x, e2[2 * q + 2]);  fma2(A[3], q1.y, e2[2 * q + 3]);
        fma2(A[4], q2.x, e2[2 * q + 4]);  fma2(A[5], q2.y, e2[2 * q + 5]);
        fma2(A[6], q3.x, e2[2 * q + 6]);  fma2(A[7], q3.y, e2[2 * q + 7]);
    }
    eacc += E - 127;
    float r = __uint_as_float((unsigned)(254 - E) << 23);
    u64 t0 = add2(add2(A[0], A[1]), add2(A[2], A[3]));
    u64 t1 = add2(add2(A[4], A[5]), add2(A[6], A[7]));
    u64 tt = add2(t0, t1);
    float lo, hi;
    unpack2(tt, lo, hi);
    pw[2 * j + p] = (lo + hi) * (gex * r);   // component p of P'[j]
}

// ---------------- kernel 2: forward scan (denominator), 128 threads ----------------
__global__ void __launch_bounds__(128, 1)
crf_scan_kernel(const float* __restrict__ logits,
                const float* __restrict__ trans,
                const float* __restrict__ start_t,
                const float* __restrict__ end_t) {
    const int b = blockIdx.x;
    const int tid = threadIdx.x;
    const int p = tid >> 6;        // i-half: warps 0-1 -> 0, warps 2-3 -> 1
    const int j = tid & 63;        // column
    const float* lg = logits + (size_t)b * SS * TT;
    const int L = g_len[b];

    // E_ij for i in this thread's half, duplicated into both f32x2 lanes
    u64 e2[32];
#pragma unroll
    for (int q = 0; q < 32; q++) {
        float e = __expf(trans[(32 * p + q) * TT + j]);
        e2[q] = pack2(e, e);
    }

    __shared__ __align__(16) float pbuf[2][2 * TT];  // float2[64] per buffer
    __shared__ float zz[2];

    // alpha0: P0[j] = exp(start+logit0), P1[j] = 0
    if (p == 0) {
        float v0 = __expf(start_t[j] + lg[j]);
        *reinterpret_cast<u64*>(&pbuf[1][2 * j]) = pack2(v0, 0.f);
    }
    int eacc = 0;

    // Two-stage pipeline: raw logit loaded 16 ahead, exp'd 8 ahead (both halves
    // duplicate per-column g — redundant but off the critical path).
    float gq[8], raw[8];
#pragma unroll
    for (int k = 0; k < 8; k++)
        gq[k] = __expf(lg[(size_t)(1 + k) * TT + j]);
#pragma unroll
    for (int k = 0; k < 8; k++)
        raw[k] = lg[(size_t)(9 + k) * TT + j];

    int t = 1;
    for (; t + 8 <= L; t += 8) {
#pragma unroll
        for (int k = 0; k < 8; k++) {
            const int rb = (1 + k) & 1;  // t stays odd: rb = (t+k)&1
            crf_stepP(e2, pbuf[rb], pbuf[rb ^ 1], p, j, gq[k], eacc);
            gq[k] = __expf(raw[k]);                  // for step t+k+8
            int nt = t + k + 16;                     // for step t+k+16
            nt = (nt < SS - 1) ? nt : (SS - 1);
            raw[k] = lg[(size_t)nt * TT + j];
        }
    }
    {
        const int rem = L - t;
#pragma unroll
        for (int k = 0; k < 8; k++) {
            if (k < rem) {
                const int rb = (1 + k) & 1;
                crf_stepP(e2, pbuf[rb], pbuf[rb ^ 1], p, j, gq[k], eacc);
            }
        }
    }

    // den = eacc*ln2 + log( sum_j (P0[j]+P1[j]) * exp(end_j) )
    __syncthreads();
    float z = 0.f;
    if (tid < 64) {
        const float* pf = pbuf[L & 1];
        z = (pf[2 * tid] + pf[2 * tid + 1]) * __expf(end_t[tid]);
    }
#pragma unroll
    for (int o = 16; o > 0; o >>= 1)
        z += __shfl_down_sync(0xffffffffu, z, o);
    if (tid < 64 && (tid & 31) == 0) zz[tid >> 5] = z;
    __syncthreads();
    if (tid == 0)
        g_den[b] = (float)eacc * 0.6931471805599453f + __logf(zz[0] + zz[1]);
}

// ---------------- kernel 3: deterministic final reduction ----------------
__global__ void crf_finish_kernel(float* __restrict__ out) {
    const int i = threadIdx.x;  // 128 threads
    float d = g_num[i] - g_den[i];
#pragma unroll
    for (int o = 16; o > 0; o >>= 1)
        d += __shfl_down_sync(0xffffffffu, d, o);
    __shared__ float ws[4];
    if ((i & 31) == 0) ws[i >> 5] = d;
    __syncthreads();
    if (i == 0) out[0] = (ws[0] + ws[1]) + (ws[2] + ws[3]);
}

// ---------------- launch ----------------
extern "C" void kernel_launch(void* const* d_in, const int* in_sizes, int n_in,
                              void* d_out, int out_size) {
    const float* logits = (const float*)d_in[0];
    const int* tags     = (const int*)d_in[1];
    const void* mask    = d_in[2];
    const float* trans  = (const float*)d_in[3];
    const float* startt = (const float*)d_in[4];
    const float* endt   = (const float*)d_in[5];
    float* out = (float*)d_out;

    crf_numer_kernel<<<BB, 1024>>>(logits, tags, mask, trans, startt, endt);
    crf_scan_kernel<<<BB, 128>>>(logits, trans, startt, endt);
    crf_finish_kernel<<<1, 128>>>(out);
}